// round 7
// baseline (speedup 1.0000x reference)
#include <cuda_runtime.h>
#include <cuda_bf16.h>
#include <cuda_fp16.h>

// Problem sizes (fixed by the reference: B=4, L=512, D=256)
#define B 4
#define L 512
#define D 256
#define D2 (D/2)              // 128 half2 pairs
#define R_SIZE (B*L*D)        // 524288 floats (r)
#define A_SIZE (B*L*L)        // 1048576 floats (alpha)

#define TILE 64               // i/j tile for scores kernel
#define NT   (L/TILE)         // 8 tiles per dim
#define NPAIR (NT*(NT+1)/2)   // 36 upper-tri tile pairs per batch
#define SH2  129              // half2 row stride; odd -> bank stride 1 -> conflict-free

// 4 MB scratch for the pre-softmax scores
__device__ float g_scores[B*L*L];

__device__ __forceinline__ __half2 tanh2_approx(__half2 x) {
    unsigned xin = *reinterpret_cast<unsigned*>(&x);
    unsigned yout;
    asm("tanh.approx.f16x2 %0, %1;" : "=r"(yout) : "r"(xin));
    return *reinterpret_cast<__half2*>(&yout);
}

// ---------------------------------------------------------------------------
// Kernel 1: scores[b,i,j] = sum_d tanh(H[b,i,d]+H[b,j,d])*w[d]
// (bias dropped: softmax is shift-invariant; only (r, alpha) are outputs)
// Symmetric => upper-triangle 64x64 tiles only, mirror on write.
// 1024 threads (2x2 micro-tile) -> 32 warps/SM for MUFU saturation.
// Inner loop: HADD2 -> tanh.approx.f16x2 -> HFMA2; fp32 flush every 4 d-pairs.
// Warp layout: tx = lane (32 cols), ty = warp id (rows); hi/w broadcast LDS,
// hj stride-129 -> conflict-free.
// ---------------------------------------------------------------------------
__global__ void __launch_bounds__(1024)
scores_kernel(const float* __restrict__ H,
              const float* __restrict__ w) {
    extern __shared__ __align__(16) unsigned smraw[];
    __half2* sHi = reinterpret_cast<__half2*>(smraw);           // 64 * SH2
    __half2* sHj = sHi + 64 * SH2;                              // 64 * SH2
    __half2* sWh = sHj + 64 * SH2;                              // D2

    const int blk = blockIdx.x;
    const int b   = blk / NPAIR;
    int p = blk % NPAIR;
    int ti = 0, rowlen = NT;
    while (p >= rowlen) { p -= rowlen; ++ti; --rowlen; }
    const int tj = ti + p;
    const int i0 = ti * TILE;
    const int j0 = tj * TILE;

    const int tid = threadIdx.x;
    const float* Hb = H + (size_t)b * L * D;

    if (tid < D2) {
        float2 wv = reinterpret_cast<const float2*>(w)[tid];
        sWh[tid] = __float22half2_rn(wv);
    }

    // Load tiles: f32 float4 from GMEM, convert to 2x half2, store to smem.
    #pragma unroll
    for (int it = 0; it < 4; ++it) {
        int e = tid + 1024 * it;         // 4096 float4 per tile
        int row = e >> 6;                // 64 float4 per row
        int c4  = e & 63;
        float4 v = *reinterpret_cast<const float4*>(Hb + (size_t)(i0 + row) * D + 4 * c4);
        sHi[row * SH2 + 2 * c4]     = __floats2half2_rn(v.x, v.y);
        sHi[row * SH2 + 2 * c4 + 1] = __floats2half2_rn(v.z, v.w);
    }
    #pragma unroll
    for (int it = 0; it < 4; ++it) {
        int e = tid + 1024 * it;
        int row = e >> 6;
        int c4  = e & 63;
        float4 v = *reinterpret_cast<const float4*>(Hb + (size_t)(j0 + row) * D + 4 * c4);
        sHj[row * SH2 + 2 * c4]     = __floats2half2_rn(v.x, v.y);
        sHj[row * SH2 + 2 * c4 + 1] = __floats2half2_rn(v.z, v.w);
    }
    __syncthreads();

    const int tx = tid & 31;     // cols tx, tx+32  (full warp spans 32 cols)
    const int ty = tid >> 5;     // rows ty, ty+32  (warp-uniform)

    float accf[2][2];
    accf[0][0] = accf[0][1] = accf[1][0] = accf[1][1] = 0.0f;

    const __half2 h2zero = __halves2half2(__ushort_as_half(0), __ushort_as_half(0));

    #pragma unroll 2
    for (int c = 0; c < D2 / 4; ++c) {      // 32 chunks of 4 d-pairs
        __half2 acc2[2][2];
        acc2[0][0] = acc2[0][1] = acc2[1][0] = acc2[1][1] = h2zero;

        #pragma unroll
        for (int u = 0; u < 4; ++u) {
            const int dp = 4 * c + u;
            const __half2 w2 = sWh[dp];
            const __half2 hi0 = sHi[ty * SH2 + dp];
            const __half2 hi1 = sHi[(ty + 32) * SH2 + dp];
            const __half2 hj0 = sHj[tx * SH2 + dp];
            const __half2 hj1 = sHj[(tx + 32) * SH2 + dp];
            acc2[0][0] = __hfma2(tanh2_approx(__hadd2(hi0, hj0)), w2, acc2[0][0]);
            acc2[0][1] = __hfma2(tanh2_approx(__hadd2(hi0, hj1)), w2, acc2[0][1]);
            acc2[1][0] = __hfma2(tanh2_approx(__hadd2(hi1, hj0)), w2, acc2[1][0]);
            acc2[1][1] = __hfma2(tanh2_approx(__hadd2(hi1, hj1)), w2, acc2[1][1]);
        }

        #pragma unroll
        for (int m = 0; m < 2; ++m)
            #pragma unroll
            for (int n = 0; n < 2; ++n) {
                float2 f = __half22float2(acc2[m][n]);
                accf[m][n] += f.x + f.y;
            }
    }

    const int mirror = (ti != tj);
    #pragma unroll
    for (int m = 0; m < 2; ++m) {
        int gi = i0 + ty + 32 * m;
        #pragma unroll
        for (int n = 0; n < 2; ++n) {
            int gj = j0 + tx + 32 * n;
            float v = accf[m][n];
            g_scores[((size_t)b * L + gi) * L + gj] = v;
            if (mirror)
                g_scores[((size_t)b * L + gj) * L + gi] = v;
        }
    }
}

// ---------------------------------------------------------------------------
// Kernel 2: warp-per-row softmax, shfl-only (no __syncthreads).
// Grid: 256 CTAs x 256 thr = 2048 warps = B*L rows. 16 elems/lane.
// ---------------------------------------------------------------------------
__global__ void __launch_bounds__(256)
softmax_kernel(float* __restrict__ out_alpha) {
    const int lane = threadIdx.x & 31;
    const int row  = blockIdx.x * 8 + (threadIdx.x >> 5);   // 0..2047
    const float4* S4 = reinterpret_cast<const float4*>(g_scores + (size_t)row * L);

    float4 v[4];
    #pragma unroll
    for (int k = 0; k < 4; ++k) v[k] = S4[lane + 32 * k];

    float mx = -1e30f;
    #pragma unroll
    for (int k = 0; k < 4; ++k)
        mx = fmaxf(mx, fmaxf(fmaxf(v[k].x, v[k].y), fmaxf(v[k].z, v[k].w)));
    #pragma unroll
    for (int o = 16; o; o >>= 1) mx = fmaxf(mx, __shfl_xor_sync(0xffffffffu, mx, o));

    float s = 0.0f;
    #pragma unroll
    for (int k = 0; k < 4; ++k) {
        v[k].x = __expf(v[k].x - mx); v[k].y = __expf(v[k].y - mx);
        v[k].z = __expf(v[k].z - mx); v[k].w = __expf(v[k].w - mx);
        s += (v[k].x + v[k].y) + (v[k].z + v[k].w);
    }
    #pragma unroll
    for (int o = 16; o; o >>= 1) s += __shfl_xor_sync(0xffffffffu, s, o);
    const float inv = 1.0f / s;

    float4* A4 = reinterpret_cast<float4*>(out_alpha + (size_t)row * L);
    #pragma unroll
    for (int k = 0; k < 4; ++k) {
        float4 o4 = make_float4(v[k].x * inv, v[k].y * inv, v[k].z * inv, v[k].w * inv);
        A4[lane + 32 * k] = o4;
    }
}

// ---------------------------------------------------------------------------
// Kernel 3: r[b] = alpha[b] (LxL) @ H[b] (LxD).
// 32x64 tiles (i x d), BK=32, 128 threads, 256 CTAs, double-buffered smem.
// Grid: (D/64, L/32, B) = (4, 16, 4).
// ---------------------------------------------------------------------------
__global__ void __launch_bounds__(128)
gemm_kernel(const float* __restrict__ alpha,
            const float* __restrict__ H,
            float* __restrict__ r) {
    __shared__ float As[2][32][36];   // [buf][k][i]
    __shared__ float Bs[2][32][68];   // [buf][k][d]

    const int b  = blockIdx.z;
    const int i0 = blockIdx.y * 32;
    const int d0 = blockIdx.x * 64;

    const float* A  = alpha + (size_t)b * L * L;
    const float* Bm = H     + (size_t)b * L * D;
    float*       C  = r     + (size_t)b * L * D;

    const int tid = threadIdx.x;
    const int tx = tid & 15;          // d group (4 floats)
    const int ty = tid >> 4;          // i group (4 rows), 0..7

    float acc[4][4];
    #pragma unroll
    for (int m = 0; m < 4; ++m)
        #pragma unroll
        for (int n = 0; n < 4; ++n) acc[m][n] = 0.0f;

    // prologue: fill buffer 0 (k0 = 0)
    #pragma unroll
    for (int t = 0; t < 2; ++t) {
        int e = tid + 128 * t;        // 256 float4 of A tile (32i x 32k)
        int ai = e >> 3, ak4 = e & 7;
        float4 v = *reinterpret_cast<const float4*>(A + (size_t)(i0 + ai) * L + 4 * ak4);
        As[0][4 * ak4 + 0][ai] = v.x;
        As[0][4 * ak4 + 1][ai] = v.y;
        As[0][4 * ak4 + 2][ai] = v.z;
        As[0][4 * ak4 + 3][ai] = v.w;
    }
    #pragma unroll
    for (int t = 0; t < 4; ++t) {
        int e = tid + 128 * t;        // 512 float4 of B tile (32k x 64d)
        int bk = e >> 4, bd4 = e & 15;
        float4 v = *reinterpret_cast<const float4*>(Bm + (size_t)bk * D + d0 + 4 * bd4);
        *reinterpret_cast<float4*>(&Bs[0][bk][4 * bd4]) = v;
    }
    __syncthreads();

    #pragma unroll 1
    for (int kt = 0; kt < 16; ++kt) {
        const int cur = kt & 1, nxt = cur ^ 1;

        float4 pa[2], pb[4];
        if (kt < 15) {
            const int k0n = (kt + 1) * 32;
            #pragma unroll
            for (int t = 0; t < 2; ++t) {
                int e = tid + 128 * t;
                int ai = e >> 3, ak4 = e & 7;
                pa[t] = *reinterpret_cast<const float4*>(A + (size_t)(i0 + ai) * L + k0n + 4 * ak4);
            }
            #pragma unroll
            for (int t = 0; t < 4; ++t) {
                int e = tid + 128 * t;
                int bk = e >> 4, bd4 = e & 15;
                pb[t] = *reinterpret_cast<const float4*>(Bm + (size_t)(k0n + bk) * D + d0 + 4 * bd4);
            }
        }

        #pragma unroll
        for (int kk = 0; kk < 32; ++kk) {
            float4 a = *reinterpret_cast<const float4*>(&As[cur][kk][ty * 4]);
            float4 bv = *reinterpret_cast<const float4*>(&Bs[cur][kk][tx * 4]);
            acc[0][0] = fmaf(a.x, bv.x, acc[0][0]);
            acc[0][1] = fmaf(a.x, bv.y, acc[0][1]);
            acc[0][2] = fmaf(a.x, bv.z, acc[0][2]);
            acc[0][3] = fmaf(a.x, bv.w, acc[0][3]);
            acc[1][0] = fmaf(a.y, bv.x, acc[1][0]);
            acc[1][1] = fmaf(a.y, bv.y, acc[1][1]);
            acc[1][2] = fmaf(a.y, bv.z, acc[1][2]);
            acc[1][3] = fmaf(a.y, bv.w, acc[1][3]);
            acc[2][0] = fmaf(a.z, bv.x, acc[2][0]);
            acc[2][1] = fmaf(a.z, bv.y, acc[2][1]);
            acc[2][2] = fmaf(a.z, bv.z, acc[2][2]);
            acc[2][3] = fmaf(a.z, bv.w, acc[2][3]);
            acc[3][0] = fmaf(a.w, bv.x, acc[3][0]);
            acc[3][1] = fmaf(a.w, bv.y, acc[3][1]);
            acc[3][2] = fmaf(a.w, bv.z, acc[3][2]);
            acc[3][3] = fmaf(a.w, bv.w, acc[3][3]);
        }

        if (kt < 15) {
            #pragma unroll
            for (int t = 0; t < 2; ++t) {
                int e = tid + 128 * t;
                int ai = e >> 3, ak4 = e & 7;
                As[nxt][4 * ak4 + 0][ai] = pa[t].x;
                As[nxt][4 * ak4 + 1][ai] = pa[t].y;
                As[nxt][4 * ak4 + 2][ai] = pa[t].z;
                As[nxt][4 * ak4 + 3][ai] = pa[t].w;
            }
            #pragma unroll
            for (int t = 0; t < 4; ++t) {
                int e = tid + 128 * t;
                int bk = e >> 4, bd4 = e & 15;
                *reinterpret_cast<float4*>(&Bs[nxt][bk][4 * bd4]) = pb[t];
            }
        }
        __syncthreads();
    }

    #pragma unroll
    for (int m = 0; m < 4; ++m) {
        int gi = i0 + ty * 4 + m;
        float4 v = make_float4(acc[m][0], acc[m][1], acc[m][2], acc[m][3]);
        *reinterpret_cast<float4*>(C + (size_t)gi * D + d0 + 4 * tx) = v;
    }
}

// ---------------------------------------------------------------------------
extern "C" void kernel_launch(void* const* d_in, const int* in_sizes, int n_in,
                              void* d_out, int out_size) {
    const float* H = (const float*)d_in[0];
    const float* w = (const float*)d_in[1];

    float* out   = (float*)d_out;
    float* r     = out;            // first R_SIZE floats
    float* alpha = out + R_SIZE;   // next A_SIZE floats

    const int smem1 = (2 * 64 * SH2 + D2) * (int)sizeof(__half2);
    cudaFuncSetAttribute(scores_kernel,
                         cudaFuncAttributeMaxDynamicSharedMemorySize, smem1);

    scores_kernel<<<B * NPAIR, 1024, smem1>>>(H, w);
    softmax_kernel<<<256, 256>>>(alpha);
    gemm_kernel<<<dim3(D / 64, L / 32, B), 128>>>(alpha, H, r);
}